// round 9
// baseline (speedup 1.0000x reference)
#include <cuda_runtime.h>

// Problem constants
#define Bq      128
#define Tq      1024
#define IN_DIM  17
#define Hq      512
#define OUT_DIM 17

// Partition: L0 blocks own NU0=12 units (G=48 gate-cols, K=512+17),
//            L1 blocks own NU1=6  units (G=24 gate-cols, K=1024).
#define NU0  12
#define NU1  6
#define NB0  43
#define NB1  86
#define NBLK (NB0 + NB1)      // 129 blocks <= 148 SMs, all co-resident

#define KC       64           // K-chunk
#define THREADS  512
#define CWARPS   12           // compute warps (warps 12..15 stage only)

// smem: Hbuf[2][KC*128] f32 (64KB) + Wbuf[2][KC*48] u64 (48KB)
#define SMEM_BYTES (2*KC*Bq*4 + 2*KC*48*8)   // 114688

typedef unsigned long long u64;

// ---------------- persistent device state ----------------
__device__ float g_h0[2][Hq * Bq];
__device__ float g_h1[2][Hq * Bq];
__device__ float g_c0[Hq * Bq];
__device__ float g_c1[Hq * Bq];
__device__ float g_xT[Tq][IN_DIM][Bq];          // x transposed [t][i][b]
__device__ float g_bias0[4 * Hq];               // bih0+bhh0
__device__ float g_bias1[4 * Hq];

// Pre-duplicated f32x2 weights: W[k][g] = {w, w}, g = gate-row 0..2047.
__device__ __align__(16) u64 g_w0d [Hq     * 4 * Hq];  // whh0  (8MB)
__device__ __align__(16) u64 g_w1i [Hq     * 4 * Hq];  // wih1  (8MB)
__device__ __align__(16) u64 g_w1h [Hq     * 4 * Hq];  // whh1  (8MB)
__device__ __align__(16) u64 g_wx0d[IN_DIM * 4 * Hq];  // wih0  (278KB)

// Grid barrier (sense reversal)
__device__ unsigned g_bar_count = 0;
__device__ volatile unsigned g_bar_gen = 0;

__device__ __forceinline__ void grid_barrier() {
    __syncthreads();
    if (threadIdx.x == 0) {
        unsigned gen = g_bar_gen;
        __threadfence();
        if (atomicAdd(&g_bar_count, 1) == NBLK - 1) {
            g_bar_count = 0;
            __threadfence();
            g_bar_gen = gen + 1;
        } else {
            while (g_bar_gen == gen) __nanosleep(64);
        }
    }
    __syncthreads();
}

__device__ __forceinline__ void fma2(u64 &a, u64 x, u64 y) {
    asm("fma.rn.f32x2 %0, %1, %2, %0;" : "+l"(a) : "l"(x), "l"(y));
}
__device__ __forceinline__ u64 pack2(float w) {
    u64 r; asm("mov.b64 %0, {%1, %1};" : "=l"(r) : "f"(w)); return r;
}
__device__ __forceinline__ void cp16(unsigned dst, const void* src) {
    asm volatile("cp.async.cg.shared.global [%0], [%1], 16;" :: "r"(dst), "l"(src));
}
#define CP_COMMIT()  asm volatile("cp.async.commit_group;")
#define CP_WAIT(n)   asm volatile("cp.async.wait_group %0;" :: "n"(n))

// ---------------- staging (all 512 threads) ----------------
__device__ __forceinline__ void stageH(unsigned hs_u32, const float* __restrict__ Hg, int kc) {
    const int n = kc * 32;                       // 16B units
    for (int i = threadIdx.x; i < n; i += THREADS)
        cp16(hs_u32 + i * 16, Hg + i * 4);
}

template<int NUc>
__device__ __forceinline__ void stageW(unsigned ws_u32, const u64* __restrict__ Wg,
                                       int k0, int kc, int u0) {
    constexpr int G = 4 * NUc, GH = G / 2, NH = NUc / 2;
    const int n = kc * GH;
    for (int i = threadIdx.x; i < n; i += THREADS) {
        int k = i / GH, cp = i - k * GH;
        int gate = cp / NH, u = (cp - gate * NH) * 2;
        int unit = u0 + u; if (unit > Hq - 2) unit = Hq - 2;   // pad clamp (even)
        cp16(ws_u32 + (unsigned)(k * G + cp * 2) * 8,
             Wg + ((size_t)(k0 + k) * (4 * Hq) + gate * Hq + unit));
    }
}

// ---------------- GEMM over K with double-buffered chunks ----------------
// acc[MAXT][hhalf][col]; compute warps: wr=wid&3 (batch row), cgl=wid>>2 (0..2).
// lane: gb=lane&7 (4-batch group), gc=lane>>3 (2-col group).
// L0 (MAXT=2): tiles T = cgl*2+{0,1}; L1 (MAXT=1): T = cgl.
template<int NUc, int MAXT>
__device__ __forceinline__ void gemm_K(const float* __restrict__ Hg,
                                       const u64* __restrict__ Wg,
                                       int u0, int K,
                                       u64 (&acc)[MAXT][2][2],
                                       float* smemf, unsigned smem_u32)
{
    constexpr int G = 4 * NUc;
    const int tid = threadIdx.x, lane = tid & 31, wid = tid >> 5;
    const int wr = wid & 3, cgl = wid >> 2;
    const int gb = lane & 7, gc = lane >> 3;
    const bool active = (wid < CWARPS);

    float* Hs0 = smemf;
    u64*   Ws0 = (u64*)(smemf + 2 * KC * Bq);
    const unsigned hs_u32 = smem_u32;
    const unsigned ws_u32 = smem_u32 + 2 * KC * Bq * 4;

    const int nch = (K + KC - 1) / KC;
    {   // prefetch chunk 0
        int kc0 = K < KC ? K : KC;
        stageH(hs_u32, Hg, kc0);
        stageW<NUc>(ws_u32, Wg, 0, kc0, u0);
        CP_COMMIT();
    }
    for (int c = 0; c < nch; ++c) {
        int kc = K - c * KC; if (kc > KC) kc = KC;
        if (c + 1 < nch) {
            int kc1 = K - (c + 1) * KC; if (kc1 > KC) kc1 = KC;
            int bi = (c + 1) & 1;
            stageH(hs_u32 + bi * KC * Bq * 4, Hg + (c + 1) * KC * Bq, kc1);
            stageW<NUc>(ws_u32 + bi * KC * G * 8, Wg, (c + 1) * KC, kc1, u0);
            CP_COMMIT();
            CP_WAIT(1);
        } else {
            CP_WAIT(0);
        }
        __syncthreads();
        if (active) {
            const float* hp = Hs0 + (c & 1) * KC * Bq + wr * 32 + gb * 4;
            const u64*   wp = Ws0 + (c & 1) * KC * G + gc * 2;
            if (kc == KC) {
                #pragma unroll 8
                for (int k = 0; k < KC; ++k) {
                    ulonglong2 h = *(const ulonglong2*)(hp + k * Bq);
                    #pragma unroll
                    for (int ti = 0; ti < MAXT; ++ti) {
                        int T = (MAXT == 2) ? (cgl * 2 + ti) : cgl;
                        ulonglong2 w = *(const ulonglong2*)(wp + k * G + T * 8);
                        fma2(acc[ti][0][0], h.x, w.x);
                        fma2(acc[ti][1][0], h.y, w.x);
                        fma2(acc[ti][0][1], h.x, w.y);
                        fma2(acc[ti][1][1], h.y, w.y);
                    }
                }
            } else {
                for (int k = 0; k < kc; ++k) {
                    ulonglong2 h = *(const ulonglong2*)(hp + k * Bq);
                    #pragma unroll
                    for (int ti = 0; ti < MAXT; ++ti) {
                        int T = (MAXT == 2) ? (cgl * 2 + ti) : cgl;
                        ulonglong2 w = *(const ulonglong2*)(wp + k * G + T * 8);
                        fma2(acc[ti][0][0], h.x, w.x);
                        fma2(acc[ti][1][0], h.y, w.x);
                        fma2(acc[ti][0][1], h.x, w.y);
                        fma2(acc[ti][1][1], h.y, w.y);
                    }
                }
            }
        }
        __syncthreads();
    }
}

// ---------------- epilogue: gates -> (c,h) ----------------
template<int NUc, int MAXT>
__device__ __forceinline__ void epilogue(int u0, u64 (&acc)[MAXT][2][2],
                                         const float* __restrict__ bias,
                                         float* __restrict__ cbuf,
                                         float* __restrict__ hdst, float* smemf)
{
    const int tid = threadIdx.x, lane = tid & 31, wid = tid >> 5;
    const int wr = wid & 3, cgl = wid >> 2;
    const int gb = lane & 7, gc = lane >> 3;

    u64* Gs2 = (u64*)smemf;                      // [c][64] u64 == [c][128] f32
    if (wid < CWARPS) {
        #pragma unroll
        for (int ti = 0; ti < MAXT; ++ti) {
            int T = (MAXT == 2) ? (cgl * 2 + ti) : cgl;
            #pragma unroll
            for (int cc = 0; cc < 2; ++cc) {
                int c = T * 8 + gc * 2 + cc;
                *(ulonglong2*)(Gs2 + c * 64 + wr * 16 + gb * 2) =
                    make_ulonglong2(acc[ti][0][cc], acc[ti][1][cc]);
            }
        }
    }
    __syncthreads();
    const float* Gf = smemf;
    const int b = tid & 127, q = tid >> 7;       // q = 0..3
    for (int u = q; u < NUc; u += 4) {
        int unit = u0 + u;
        if (unit < Hq) {
            float gi = Gf[(u          ) * Bq + b] + bias[unit         ];
            float gf = Gf[(u +     NUc) * Bq + b] + bias[unit +     Hq];
            float gg = Gf[(u + 2 * NUc) * Bq + b] + bias[unit + 2 * Hq];
            float go = Gf[(u + 3 * NUc) * Bq + b] + bias[unit + 3 * Hq];
            float ig = 1.f / (1.f + __expf(-gi));
            float fg = 1.f / (1.f + __expf(-gf));
            float og = 1.f / (1.f + __expf(-go));
            float gv = tanhf(gg);
            int off = unit * Bq + b;
            float cn = fg * cbuf[off] + ig * gv;
            cbuf[off] = cn;
            __stcg(&hdst[off], og * tanhf(cn));
        }
    }
    __syncthreads();
}

// ---------------- persistent kernel ----------------
__global__ void __launch_bounds__(THREADS, 1)
lstm_persistent(const float* __restrict__ x,
                const float* __restrict__ wih0, const float* __restrict__ whh0,
                const float* __restrict__ bih0, const float* __restrict__ bhh0,
                const float* __restrict__ wih1, const float* __restrict__ whh1,
                const float* __restrict__ bih1, const float* __restrict__ bhh1,
                const float* __restrict__ lin_w, const float* __restrict__ lin_b,
                float* __restrict__ out)
{
    extern __shared__ float smemf[];
    const unsigned smem_u32 = (unsigned)__cvta_generic_to_shared(smemf);
    const int blk = blockIdx.x, tid = threadIdx.x;

    // ---- one-time init ----
    {
        const int gi = blk * THREADS + tid, gs = NBLK * THREADS;
        for (int i = gi; i < 2 * Hq * Bq; i += gs) {
            ((float*)g_h0)[i] = 0.f;  ((float*)g_h1)[i] = 0.f;
        }
        for (int i = gi; i < Hq * Bq; i += gs) { g_c0[i] = 0.f; g_c1[i] = 0.f; }
        for (int g = gi; g < 4 * Hq; g += gs) {
            g_bias0[g] = bih0[g] + bhh0[g];
            g_bias1[g] = bih1[g] + bhh1[g];
        }
        const int NX = Bq * Tq * IN_DIM;
        for (int i = gi; i < NX; i += gs) {
            int b = i / (Tq * IN_DIM);
            int r = i - b * (Tq * IN_DIM);
            int t = r / IN_DIM, ii = r - t * IN_DIM;
            g_xT[t][ii][b] = x[i];
        }
        for (int i = gi; i < Hq * 4 * Hq; i += gs) {
            int k = i >> 11, g = i & (4 * Hq - 1);
            g_w0d[i] = pack2(whh0[(size_t)g * Hq + k]);
            g_w1i[i] = pack2(wih1[(size_t)g * Hq + k]);
            g_w1h[i] = pack2(whh1[(size_t)g * Hq + k]);
        }
        for (int i = gi; i < IN_DIM * 4 * Hq; i += gs) {
            int k = i >> 11, g = i & (4 * Hq - 1);
            g_wx0d[i] = pack2(wih0[(size_t)g * IN_DIM + k]);
        }
    }
    grid_barrier();

    // ---- pipelined recurrence: L0 step t || L1 step t-1 ----
    if (blk < NB0) {
        const int u0 = blk * NU0;
        #pragma unroll 1
        for (int t = 0; t <= Tq; ++t) {
            if (t < Tq) {
                u64 acc[2][2][2];
                #pragma unroll
                for (int a = 0; a < 2; ++a)
                    #pragma unroll
                    for (int bb = 0; bb < 2; ++bb)
                        #pragma unroll
                        for (int cc = 0; cc < 2; ++cc) acc[a][bb][cc] = 0ull;
                gemm_K<NU0, 2>(g_h0[(t + 1) & 1], g_w0d,  u0, Hq,     acc, smemf, smem_u32);
                gemm_K<NU0, 2>(&g_xT[t][0][0],    g_wx0d, u0, IN_DIM, acc, smemf, smem_u32);
                epilogue<NU0, 2>(u0, acc, g_bias0, g_c0, g_h0[t & 1], smemf);
            }
            grid_barrier();
        }
    } else {
        const int u0 = (blk - NB0) * NU1;
        #pragma unroll 1
        for (int t = 0; t <= Tq; ++t) {
            if (t >= 1) {
                const int s = t - 1;
                u64 acc[1][2][2];
                #pragma unroll
                for (int bb = 0; bb < 2; ++bb)
                    #pragma unroll
                    for (int cc = 0; cc < 2; ++cc) acc[0][bb][cc] = 0ull;
                gemm_K<NU1, 1>(g_h0[s & 1],       g_w1i, u0, Hq, acc, smemf, smem_u32);
                gemm_K<NU1, 1>(g_h1[(s + 1) & 1], g_w1h, u0, Hq, acc, smemf, smem_u32);
                epilogue<NU1, 1>(u0, acc, g_bias1, g_c1, g_h1[s & 1], smemf);
            }
            grid_barrier();
        }
    }

    // ---- final linear: out[b][o] = h1_last[:,b] . lin_w[o,:] + lin_b[o] ----
    if (blk < OUT_DIM && tid < Bq) {
        const int o = blk, b = tid;
        const float* h = g_h1[(Tq - 1) & 1];
        float a = __ldg(&lin_b[o]);
        #pragma unroll 8
        for (int k = 0; k < Hq; ++k)
            a += __ldcg(&h[k * Bq + b]) * __ldg(&lin_w[o * Hq + k]);
        out[b * OUT_DIM + o] = a;
    }
}

extern "C" void kernel_launch(void* const* d_in, const int* in_sizes, int n_in,
                              void* d_out, int out_size)
{
    const float* x     = (const float*)d_in[0];
    const float* wih0  = (const float*)d_in[1];
    const float* whh0  = (const float*)d_in[2];
    const float* bih0  = (const float*)d_in[3];
    const float* bhh0  = (const float*)d_in[4];
    const float* wih1  = (const float*)d_in[5];
    const float* whh1  = (const float*)d_in[6];
    const float* bih1  = (const float*)d_in[7];
    const float* bhh1  = (const float*)d_in[8];
    const float* lin_w = (const float*)d_in[9];
    const float* lin_b = (const float*)d_in[10];
    float* out = (float*)d_out;

    cudaFuncSetAttribute(lstm_persistent,
                         cudaFuncAttributeMaxDynamicSharedMemorySize, SMEM_BYTES);

    lstm_persistent<<<NBLK, THREADS, SMEM_BYTES>>>(
        x, wih0, whh0, bih0, bhh0, wih1, whh1, bih1, bhh1, lin_w, lin_b, out);
}

// round 12
// speedup vs baseline: 1.2747x; 1.2747x over previous
#include <cuda_runtime.h>

// Problem constants
#define Bq      128
#define Tq      1024
#define IN_DIM  17
#define Hq      512
#define OUT_DIM 17

// Partition: L0 blocks own NU0=12 units (G=48 gate-cols, K=512+17),
//            L1 blocks own NU1=6  units (G=24 gate-cols, K=1024).
#define NU0  12
#define NU1  6
#define NB0  43
#define NB1  86
#define NBLK (NB0 + NB1)      // 129 blocks <= 148 SMs, all co-resident

#define KC       64           // K-chunk rows (each row = 128 f32 = 512B)
#define THREADS  512
#define CWARPS   12           // warps 0..11 compute; warp 15 lane 0 = DMA

// smem layout (bytes):
//   [0, 65536)        Hbuf[2][KC*128] f32  (epilogue reuses Hbuf[0] for gates)
//   [65536, 65552)    mbar[2] (u64 each)
//   [65600, ...)      resident weights
//       L0: Whh slice [512][48] f32 (98304) + Wih slice [17][48] f32 (3264)
//       L1: Wih1 slice [512][24] f32 (49152) + Whh1 slice [512][24] f32 (49152)
#define SMEM_MBAR_OFF  (2*KC*Bq*4)             // 65536
#define SMEM_W_OFF     (SMEM_MBAR_OFF + 64)    // 65600 (16B aligned)
#define SMEM_BYTES     (SMEM_W_OFF + 512*48*4 + 17*48*4)   // 167168

typedef unsigned long long u64;

// ---------------- persistent device state ----------------
__device__ __align__(128) float g_h0[2][Hq * Bq];
__device__ __align__(128) float g_h1[2][Hq * Bq];
__device__ __align__(128) float g_c0[Hq * Bq];
__device__ __align__(128) float g_c1[Hq * Bq];
__device__ __align__(128) float g_xT[Tq][IN_DIM][Bq];   // x transposed [t][i][b]
__device__ float g_bias0[4 * Hq];                        // bih0+bhh0
__device__ float g_bias1[4 * Hq];

// Grid barrier (sense reversal)
__device__ unsigned g_bar_count = 0;
__device__ volatile unsigned g_bar_gen = 0;

__device__ __forceinline__ void grid_barrier() {
    __syncthreads();
    if (threadIdx.x == 0) {
        unsigned gen = g_bar_gen;
        __threadfence();
        if (atomicAdd(&g_bar_count, 1) == NBLK - 1) {
            g_bar_count = 0;
            __threadfence();
            g_bar_gen = gen + 1;
        } else {
            while (g_bar_gen == gen) __nanosleep(64);
        }
    }
    __syncthreads();
}

__device__ __forceinline__ void fma2(u64 &a, u64 x, u64 y) {
    asm("fma.rn.f32x2 %0, %1, %2, %0;" : "+l"(a) : "l"(x), "l"(y));
}
__device__ __forceinline__ u64 pack2(float w) {
    u64 r; asm("mov.b64 %0, {%1, %1};" : "=l"(r) : "f"(w)); return r;
}

// ---------------- mbarrier + bulk-copy primitives ----------------
__device__ __forceinline__ void mbar_init(unsigned mbar, unsigned count) {
    asm volatile("mbarrier.init.shared.b64 [%0], %1;" :: "r"(mbar), "r"(count) : "memory");
}
__device__ __forceinline__ void mbar_expect(unsigned mbar, unsigned bytes) {
    asm volatile("mbarrier.arrive.expect_tx.shared.b64 _, [%0], %1;"
                 :: "r"(mbar), "r"(bytes) : "memory");
}
__device__ __forceinline__ void bulk_g2s(unsigned dst, const void* src,
                                         unsigned bytes, unsigned mbar) {
    asm volatile("cp.async.bulk.shared::cta.global.mbarrier::complete_tx::bytes "
                 "[%0], [%1], %2, [%3];"
                 :: "r"(dst), "l"(src), "r"(bytes), "r"(mbar) : "memory");
}
__device__ __forceinline__ void mbar_wait(unsigned mbar, unsigned phase) {
    asm volatile(
        "{\n\t.reg .pred P;\n\t"
        "WAIT_%=:\n\t"
        "mbarrier.try_wait.parity.acquire.cta.shared::cta.b64 P, [%0], %1, 0x989680;\n\t"
        "@P bra DONE_%=;\n\t"
        "bra WAIT_%=;\n\t"
        "DONE_%=:\n\t}"
        :: "r"(mbar), "r"(phase) : "memory");
}

// ---------------- GEMM over K: resident W (smem), H via TMA double-buffer ----
// Compute warps 0..11: wr = wid&3 (batch quarter), cgl = wid>>2 (0..2).
// Lane: gb = lane&7 (4-batch group), gc = lane>>3 (MAXJ-col group).
// Thread tile: 4 batches (2 f32x2) x MAXJ cols. Col base = cgl*4*MAXJ + gc*MAXJ.
template<int NUc, int MAXJ>
__device__ __forceinline__ void gemm_res(const float* __restrict__ Hg,   // global H [k][b]
                                         const float* __restrict__ Wr,   // resident smem [k][G]
                                         int K, u64 (&acc)[MAXJ][2],
                                         float* Hs, unsigned hs_u32,
                                         unsigned mb0, unsigned mb1,
                                         int &ph0, int &ph1)
{
    constexpr int G = 4 * NUc;
    const int tid = threadIdx.x, lane = tid & 31, wid = tid >> 5;
    const int wr = wid & 3, cgl = wid >> 2;
    const int gb = lane & 7, gc = lane >> 3;
    const bool dma = (tid == 480);           // warp 15 lane 0
    const bool comp = (wid < CWARPS);
    const int nch = (K + KC - 1) / KC;

    if (dma) {
        int kc0 = K < KC ? K : KC;
        mbar_expect(mb0, kc0 * Bq * 4);
        bulk_g2s(hs_u32, Hg, kc0 * Bq * 4, mb0);
        if (nch > 1) {
            int kc1 = K - KC < KC ? K - KC : KC;
            mbar_expect(mb1, kc1 * Bq * 4);
            bulk_g2s(hs_u32 + KC * Bq * 4, Hg + KC * Bq, kc1 * Bq * 4, mb1);
        }
    }
    for (int c = 0; c < nch; ++c) {
        int kc = K - c * KC; if (kc > KC) kc = KC;
        if (comp) {
            if (c & 1) { mbar_wait(mb1, ph1); ph1 ^= 1; }
            else       { mbar_wait(mb0, ph0); ph0 ^= 1; }
            const float* hp = Hs + (c & 1) * KC * Bq + wr * 32 + gb * 4;
            const float* wp = Wr + c * KC * G + cgl * 4 * MAXJ + gc * MAXJ;
            if (kc == KC) {
                #pragma unroll 8
                for (int k = 0; k < KC; ++k) {
                    ulonglong2 h = *(const ulonglong2*)(hp + k * Bq);
                    if (MAXJ == 4) {
                        float4 w = *(const float4*)(wp + k * G);
                        u64 w0 = pack2(w.x), w1 = pack2(w.y), w2 = pack2(w.z), w3 = pack2(w.w);
                        fma2(acc[0][0], h.x, w0); fma2(acc[0][1], h.y, w0);
                        fma2(acc[1][0], h.x, w1); fma2(acc[1][1], h.y, w1);
                        fma2(acc[2][0], h.x, w2); fma2(acc[2][1], h.y, w2);
                        fma2(acc[3][0], h.x, w3); fma2(acc[3][1], h.y, w3);
                    } else {
                        float2 w = *(const float2*)(wp + k * G);
                        u64 w0 = pack2(w.x), w1 = pack2(w.y);
                        fma2(acc[0][0], h.x, w0); fma2(acc[0][1], h.y, w0);
                        fma2(acc[1][0], h.x, w1); fma2(acc[1][1], h.y, w1);
                    }
                }
            } else {
                for (int k = 0; k < kc; ++k) {
                    ulonglong2 h = *(const ulonglong2*)(hp + k * Bq);
                    if (MAXJ == 4) {
                        float4 w = *(const float4*)(wp + k * G);
                        u64 w0 = pack2(w.x), w1 = pack2(w.y), w2 = pack2(w.z), w3 = pack2(w.w);
                        fma2(acc[0][0], h.x, w0); fma2(acc[0][1], h.y, w0);
                        fma2(acc[1][0], h.x, w1); fma2(acc[1][1], h.y, w1);
                        fma2(acc[2][0], h.x, w2); fma2(acc[2][1], h.y, w2);
                        fma2(acc[3][0], h.x, w3); fma2(acc[3][1], h.y, w3);
                    } else {
                        float2 w = *(const float2*)(wp + k * G);
                        u64 w0 = pack2(w.x), w1 = pack2(w.y);
                        fma2(acc[0][0], h.x, w0); fma2(acc[0][1], h.y, w0);
                        fma2(acc[1][0], h.x, w1); fma2(acc[1][1], h.y, w1);
                    }
                }
            }
        }
        __syncthreads();
        if (dma && c + 2 < nch) {
            int kc2 = K - (c + 2) * KC; if (kc2 > KC) kc2 = KC;
            unsigned b = (unsigned)(c & 1);
            unsigned mbx = b ? mb1 : mb0;
            mbar_expect(mbx, kc2 * Bq * 4);
            bulk_g2s(hs_u32 + b * KC * Bq * 4, Hg + (c + 2) * KC * Bq, kc2 * Bq * 4, mbx);
        }
    }
}

// ---------------- epilogue: gates -> (c,h) ----------------
template<int NUc, int MAXJ>
__device__ __forceinline__ void epilogue(int u0, u64 (&acc)[MAXJ][2],
                                         const float* __restrict__ bias,
                                         float* __restrict__ cbuf,
                                         float* __restrict__ hdst, float* smemf)
{
    const int tid = threadIdx.x, lane = tid & 31, wid = tid >> 5;
    const int wr = wid & 3, cgl = wid >> 2;
    const int gb = lane & 7, gc = lane >> 3;

    // Gate column c = 128 f32 = 32 ulonglong2 -> stride 32 (BUG FIX: was 16).
    ulonglong2* Gs2 = (ulonglong2*)smemf;
    if (wid < CWARPS) {
        const int cb = cgl * 4 * MAXJ + gc * MAXJ;
        #pragma unroll
        for (int j = 0; j < MAXJ; ++j) {
            int c = cb + j;
            Gs2[c * 32 + wr * 8 + gb] = make_ulonglong2(acc[j][0], acc[j][1]);
        }
    }
    __syncthreads();
    const float* Gf = smemf;
    const int b = tid & 127, q = tid >> 7;      // q = 0..3
    for (int u = q; u < NUc; u += 4) {
        int unit = u0 + u;
        if (unit < Hq) {
            float gi = Gf[(u          ) * Bq + b] + bias[unit         ];
            float gf = Gf[(u +     NUc) * Bq + b] + bias[unit +     Hq];
            float gg = Gf[(u + 2 * NUc) * Bq + b] + bias[unit + 2 * Hq];
            float go = Gf[(u + 3 * NUc) * Bq + b] + bias[unit + 3 * Hq];
            float ig = 1.f / (1.f + __expf(-gi));
            float fg = 1.f / (1.f + __expf(-gf));
            float og = 1.f / (1.f + __expf(-go));
            float gv = tanhf(gg);
            int off = unit * Bq + b;
            float cn = fg * cbuf[off] + ig * gv;
            cbuf[off] = cn;
            __stcg(&hdst[off], og * tanhf(cn));
        }
    }
    __syncthreads();
}

// ---------------- persistent kernel ----------------
__global__ void __launch_bounds__(THREADS, 1)
lstm_persistent(const float* __restrict__ x,
                const float* __restrict__ wih0, const float* __restrict__ whh0,
                const float* __restrict__ bih0, const float* __restrict__ bhh0,
                const float* __restrict__ wih1, const float* __restrict__ whh1,
                const float* __restrict__ bih1, const float* __restrict__ bhh1,
                const float* __restrict__ lin_w, const float* __restrict__ lin_b,
                float* __restrict__ out)
{
    extern __shared__ float smemf[];
    const unsigned smem_u32 = (unsigned)__cvta_generic_to_shared(smemf);
    const unsigned hs_u32 = smem_u32;
    const unsigned mb0 = smem_u32 + SMEM_MBAR_OFF, mb1 = mb0 + 8;
    float* Hs  = smemf;
    float* Wsm = smemf + SMEM_W_OFF / 4;
    const int blk = blockIdx.x, tid = threadIdx.x;

    // ---- one-time init: states, biases, x transpose (distributed) ----
    {
        const int gi = blk * THREADS + tid, gs = NBLK * THREADS;
        for (int i = gi; i < 2 * Hq * Bq; i += gs) {
            ((float*)g_h0)[i] = 0.f;  ((float*)g_h1)[i] = 0.f;
        }
        for (int i = gi; i < Hq * Bq; i += gs) { g_c0[i] = 0.f; g_c1[i] = 0.f; }
        for (int g = gi; g < 4 * Hq; g += gs) {
            g_bias0[g] = bih0[g] + bhh0[g];
            g_bias1[g] = bih1[g] + bhh1[g];
        }
        const int NX = Bq * Tq * IN_DIM;
        for (int i = gi; i < NX; i += gs) {
            int b = i / (Tq * IN_DIM);
            int r = i - b * (Tq * IN_DIM);
            int t = r / IN_DIM, ii = r - t * IN_DIM;
            g_xT[t][ii][b] = x[i];
        }
    }
    // ---- per-block resident weight load (one-time) ----
    if (blk < NB0) {
        const int u0 = blk * NU0;
        for (int i = tid; i < Hq * 48; i += THREADS) {
            int k = i / 48, c = i - (i / 48) * 48;
            int unit = u0 + (c % NU0); if (unit > Hq - 1) unit = Hq - 1;
            int row = (c / NU0) * Hq + unit;
            Wsm[i] = whh0[(size_t)row * Hq + k];
        }
        for (int i = tid; i < IN_DIM * 48; i += THREADS) {
            int k = i / 48, c = i - (i / 48) * 48;
            int unit = u0 + (c % NU0); if (unit > Hq - 1) unit = Hq - 1;
            int row = (c / NU0) * Hq + unit;
            Wsm[Hq * 48 + i] = wih0[(size_t)row * IN_DIM + k];
        }
    } else {
        const int u0 = (blk - NB0) * NU1;
        for (int i = tid; i < Hq * 24; i += THREADS) {
            int k = i / 24, c = i - (i / 24) * 24;
            int unit = u0 + (c % NU1); if (unit > Hq - 1) unit = Hq - 1;
            int row = (c / NU1) * Hq + unit;
            Wsm[i]           = wih1[(size_t)row * Hq + k];
            Wsm[Hq * 24 + i] = whh1[(size_t)row * Hq + k];
        }
    }
    if (tid == 0) { mbar_init(mb0, 1); mbar_init(mb1, 1); }
    __syncthreads();
    asm volatile("fence.proxy.async.shared::cta;" ::: "memory");
    grid_barrier();

    int ph0 = 0, ph1 = 0;

    // ---- pipelined recurrence: L0 step t || L1 step t-1 ----
    if (blk < NB0) {
        const int u0 = blk * NU0;
        #pragma unroll 1
        for (int t = 0; t <= Tq; ++t) {
            if (t < Tq) {
                u64 acc[4][2];
                #pragma unroll
                for (int j = 0; j < 4; ++j) { acc[j][0] = 0ull; acc[j][1] = 0ull; }
                gemm_res<NU0, 4>(g_h0[(t + 1) & 1], Wsm, Hq, acc,
                                 Hs, hs_u32, mb0, mb1, ph0, ph1);
                gemm_res<NU0, 4>(&g_xT[t][0][0], Wsm + Hq * 48, IN_DIM, acc,
                                 Hs, hs_u32, mb0, mb1, ph0, ph1);
                epilogue<NU0, 4>(u0, acc, g_bias0, g_c0, g_h0[t & 1], smemf);
            }
            grid_barrier();
        }
    } else {
        const int u0 = (blk - NB0) * NU1;
        #pragma unroll 1
        for (int t = 0; t <= Tq; ++t) {
            if (t >= 1) {
                const int s = t - 1;
                u64 acc[2][2];
                #pragma unroll
                for (int j = 0; j < 2; ++j) { acc[j][0] = 0ull; acc[j][1] = 0ull; }
                gemm_res<NU1, 2>(g_h0[s & 1], Wsm, Hq, acc,
                                 Hs, hs_u32, mb0, mb1, ph0, ph1);
                gemm_res<NU1, 2>(g_h1[(s + 1) & 1], Wsm + Hq * 24, Hq, acc,
                                 Hs, hs_u32, mb0, mb1, ph0, ph1);
                epilogue<NU1, 2>(u0, acc, g_bias1, g_c1, g_h1[s & 1], smemf);
            }
            grid_barrier();
        }
    }

    // ---- final linear: out[b][o] = h1_last[:,b] . lin_w[o,:] + lin_b[o] ----
    if (blk < OUT_DIM && tid < Bq) {
        const int o = blk, b = tid;
        const float* h = g_h1[(Tq - 1) & 1];
        float a = __ldg(&lin_b[o]);
        #pragma unroll 8
        for (int k = 0; k < Hq; ++k)
            a += __ldcg(&h[k * Bq + b]) * __ldg(&lin_w[o * Hq + k]);
        out[b * OUT_DIM + o] = a;
    }
}

extern "C" void kernel_launch(void* const* d_in, const int* in_sizes, int n_in,
                              void* d_out, int out_size)
{
    const float* x     = (const float*)d_in[0];
    const float* wih0  = (const float*)d_in[1];
    const float* whh0  = (const float*)d_in[2];
    const float* bih0  = (const float*)d_in[3];
    const float* bhh0  = (const float*)d_in[4];
    const float* wih1  = (const float*)d_in[5];
    const float* whh1  = (const float*)d_in[6];
    const float* bih1  = (const float*)d_in[7];
    const float* bhh1  = (const float*)d_in[8];
    const float* lin_w = (const float*)d_in[9];
    const float* lin_b = (const float*)d_in[10];
    float* out = (float*)d_out;

    cudaFuncSetAttribute(lstm_persistent,
                         cudaFuncAttributeMaxDynamicSharedMemorySize, SMEM_BYTES);

    lstm_persistent<<<NBLK, THREADS, SMEM_BYTES>>>(
        x, wih0, whh0, bih0, bhh0, wih1, whh1, bih1, bhh1, lin_w, lin_b, out);
}